// round 3
// baseline (speedup 1.0000x reference)
#include <cuda_runtime.h>

// ---------------------------------------------------------------------------
// DeepFeatureMatcher: mutual-NN matching with ratio test.
//   d1 = normalize(map_A.reshape(512,-1).T)   (12288 x 512)
//   d2 = normalize(map_B.reshape(512,-1).T)
//   sim = d1 @ d2.T; top-2 both directions; mutual + ratio<=0.95 mask.
// Output (float32, 3*12288): [masked_sim | nn12 as float | mask as 0/1]
// Strategy: fused fp32 SGEMM + streaming bidirectional top-2 (sim never
// materialized; GEMM computed once for both directions).
// ---------------------------------------------------------------------------

#define N_DESC 12288
#define CH     512
#define BM     128
#define BN     128
#define BK     16
#define TM     8
#define TN     8
#define NTHREADS 256
#define CS     3                    // column chunks
#define CHUNK  (N_DESC / CS)        // 4096
#define NROWTILES (N_DESC / BM)     // 96
#define RATIO_T 0.95f
#define EPS_T   1e-8f

// ---- scratch (device globals: no allocation allowed) ----------------------
__device__ float g_dA[CH * N_DESC];      // normalized A, channel-major (512,12288)
__device__ float g_dB[CH * N_DESC];      // normalized B
__device__ float g_rnA[N_DESC];
__device__ float g_rnB[N_DESC];
// row-direction (A->B) partial top2: [CS][N]
__device__ float g_rowV1[CS * N_DESC];
__device__ float g_rowV2[CS * N_DESC];
__device__ int   g_rowI1[CS * N_DESC];
// col-direction (B->A) partial top2: [NROWTILES][N]
__device__ float g_colV1[NROWTILES * N_DESC];
__device__ float g_colV2[NROWTILES * N_DESC];
__device__ int   g_colI1[NROWTILES * N_DESC];
// fully reduced top2, both directions
__device__ float g_aV1[N_DESC]; __device__ float g_aV2[N_DESC]; __device__ int g_aI1[N_DESC];
__device__ float g_bV1[N_DESC]; __device__ float g_bV2[N_DESC]; __device__ int g_bI1[N_DESC];

// ---- kernel 1: per-descriptor inverse norms -------------------------------
__global__ void norms_kernel(const float* __restrict__ mA,
                             const float* __restrict__ mB) {
    int i = blockIdx.x * blockDim.x + threadIdx.x;
    if (i >= N_DESC) return;
    const float* m = blockIdx.y ? mB : mA;
    float s = 0.f;
    #pragma unroll 8
    for (int c = 0; c < CH; ++c) {
        float v = m[c * N_DESC + i];   // coalesced: i is the fast axis
        s = fmaf(v, v, s);
    }
    float r = 1.0f / sqrtf(s);
    if (blockIdx.y) g_rnB[i] = r; else g_rnA[i] = r;
}

// ---- kernel 2: write normalized descriptors (same channel-major layout) ---
__global__ void scale_kernel(const float* __restrict__ mA,
                             const float* __restrict__ mB) {
    int i = blockIdx.x * blockDim.x + threadIdx.x;   // descriptor
    int c = blockIdx.y;                              // channel
    if (i >= N_DESC) return;
    if (blockIdx.z == 0)
        g_dA[c * N_DESC + i] = mA[c * N_DESC + i] * g_rnA[i];
    else
        g_dB[c * N_DESC + i] = mB[c * N_DESC + i] * g_rnB[i];
}

// ---- kernel 3: fused GEMM + bidirectional streaming top-2 -----------------
// Block = (rowTile, colChunk). Computes 128 A-rows vs 4096 B-cols.
// Global->smem path is register-staged: next K-tile is prefetched into
// registers while the current smem tile feeds the FMA loop.
__global__ __launch_bounds__(NTHREADS, 2)
void gemm_top2_kernel() {
    __shared__ float Xs[BK * BM];
    __shared__ float Ys[BK * BN];
    __shared__ float cv1[16 * BN];
    __shared__ float cv2[16 * BN];
    __shared__ int   ci1[16 * BN];
    __shared__ float rv1[BM];
    __shared__ float rv2[BM];
    __shared__ int   ri1[BM];

    const int tid = threadIdx.x;
    const int tx = tid & 15;        // column group
    const int ty = tid >> 4;        // row group
    const int rowTile = blockIdx.x;
    const int chunk   = blockIdx.y;
    const int i0 = rowTile * BM;
    const int jStart = chunk * CHUNK;

    // fixed per-thread staging coords: two float4 slots per matrix per tile
    const int s0  = tid * 2;
    const int kk0 = s0 >> 5,       m40 = s0 & 31;
    const int kk1 = (s0 + 1) >> 5, m41 = (s0 + 1) & 31;

    if (tid < BM) { rv1[tid] = -2.f; rv2[tid] = -2.f; ri1[tid] = 0; }
    __syncthreads();

    for (int jt = 0; jt < CHUNK / BN; ++jt) {
        const int j0 = jStart + jt * BN;
        float acc[TM][TN];
        #pragma unroll
        for (int r = 0; r < TM; ++r)
            #pragma unroll
            for (int c = 0; c < TN; ++c) acc[r][c] = 0.f;

        // preload first K-tile into registers
        float4 pa0 = *reinterpret_cast<const float4*>(&g_dA[kk0 * N_DESC + i0 + m40 * 4]);
        float4 pa1 = *reinterpret_cast<const float4*>(&g_dA[kk1 * N_DESC + i0 + m41 * 4]);
        float4 pb0 = *reinterpret_cast<const float4*>(&g_dB[kk0 * N_DESC + j0 + m40 * 4]);
        float4 pb1 = *reinterpret_cast<const float4*>(&g_dB[kk1 * N_DESC + j0 + m41 * 4]);

        for (int k0 = 0; k0 < CH; k0 += BK) {
            // commit staged registers to smem
            *reinterpret_cast<float4*>(&Xs[kk0 * BM + m40 * 4]) = pa0;
            *reinterpret_cast<float4*>(&Xs[kk1 * BM + m41 * 4]) = pa1;
            *reinterpret_cast<float4*>(&Ys[kk0 * BN + m40 * 4]) = pb0;
            *reinterpret_cast<float4*>(&Ys[kk1 * BN + m41 * 4]) = pb1;
            __syncthreads();

            // prefetch next K-tile (LDG overlapped with the FMA loop below)
            if (k0 + BK < CH) {
                const int kn = k0 + BK;
                pa0 = *reinterpret_cast<const float4*>(&g_dA[(kn + kk0) * N_DESC + i0 + m40 * 4]);
                pa1 = *reinterpret_cast<const float4*>(&g_dA[(kn + kk1) * N_DESC + i0 + m41 * 4]);
                pb0 = *reinterpret_cast<const float4*>(&g_dB[(kn + kk0) * N_DESC + j0 + m40 * 4]);
                pb1 = *reinterpret_cast<const float4*>(&g_dB[(kn + kk1) * N_DESC + j0 + m41 * 4]);
            }

            #pragma unroll
            for (int kk = 0; kk < BK; ++kk) {
                float4 a0 = *reinterpret_cast<const float4*>(&Xs[kk * BM + ty * 8]);
                float4 a1 = *reinterpret_cast<const float4*>(&Xs[kk * BM + ty * 8 + 4]);
                float4 b0 = *reinterpret_cast<const float4*>(&Ys[kk * BN + tx * 8]);
                float4 b1 = *reinterpret_cast<const float4*>(&Ys[kk * BN + tx * 8 + 4]);
                float a[8] = {a0.x,a0.y,a0.z,a0.w,a1.x,a1.y,a1.z,a1.w};
                float b[8] = {b0.x,b0.y,b0.z,b0.w,b1.x,b1.y,b1.z,b1.w};
                #pragma unroll
                for (int r = 0; r < TM; ++r)
                    #pragma unroll
                    for (int c = 0; c < TN; ++c)
                        acc[r][c] = fmaf(a[r], b[c], acc[r][c]);
            }
            __syncthreads();
        }

        // ---- row top2 (A->B): reduce over the 16 tx-threads per row -------
        #pragma unroll
        for (int r = 0; r < TM; ++r) {
            float v1 = -2.f, v2 = -2.f; int i1 = 0;
            #pragma unroll
            for (int c = 0; c < TN; ++c) {
                float v = acc[r][c];
                int idx = j0 + tx * 8 + c;
                if (v > v1) { v2 = v1; v1 = v; i1 = idx; }
                else if (v > v2) v2 = v;
            }
            // tx occupies lane bits 0..3 -> xor butterfly stays in-row
            #pragma unroll
            for (int m = 8; m > 0; m >>= 1) {
                float w1 = __shfl_xor_sync(0xffffffffu, v1, m);
                int   j1 = __shfl_xor_sync(0xffffffffu, i1, m);
                float w2 = __shfl_xor_sync(0xffffffffu, v2, m);
                if (w1 > v1) { v2 = fmaxf(v1, w2); v1 = w1; i1 = j1; }
                else         { v2 = fmaxf(v2, w1); }
            }
            if (tx == 0) {   // single writer per row -> no race
                int row = ty * 8 + r;
                float o1 = rv1[row], o2 = rv2[row]; int oi = ri1[row];
                if (v1 > o1) { o2 = fmaxf(o1, v2); o1 = v1; oi = i1; }
                else         { o2 = fmaxf(o2, v1); }
                rv1[row] = o1; rv2[row] = o2; ri1[row] = oi;
            }
        }

        // ---- col top2 (B->A), partial over this tile's 128 rows -----------
        #pragma unroll
        for (int c = 0; c < TN; ++c) {
            float v1 = -2.f, v2 = -2.f; int i1 = 0;
            #pragma unroll
            for (int r = 0; r < TM; ++r) {
                float v = acc[r][c];
                int idx = i0 + ty * 8 + r;
                if (v > v1) { v2 = v1; v1 = v; i1 = idx; }
                else if (v > v2) v2 = v;
            }
            int col = tx * 8 + c;
            cv1[ty * BN + col] = v1;
            cv2[ty * BN + col] = v2;
            ci1[ty * BN + col] = i1;
        }
        __syncthreads();
        if (tid < BN) {
            float v1 = cv1[tid], v2 = cv2[tid]; int i1 = ci1[tid];
            #pragma unroll
            for (int t = 1; t < 16; ++t) {
                float w1 = cv1[t * BN + tid];
                float w2 = cv2[t * BN + tid];
                int   j1 = ci1[t * BN + tid];
                if (w1 > v1) { v2 = fmaxf(v1, w2); v1 = w1; i1 = j1; }
                else         { v2 = fmaxf(v2, w1); }
            }
            int j = j0 + tid;
            g_colV1[rowTile * N_DESC + j] = v1;
            g_colV2[rowTile * N_DESC + j] = v2;
            g_colI1[rowTile * N_DESC + j] = i1;
        }
        __syncthreads();
    }

    if (tid < BM) {
        g_rowV1[chunk * N_DESC + i0 + tid] = rv1[tid];
        g_rowV2[chunk * N_DESC + i0 + tid] = rv2[tid];
        g_rowI1[chunk * N_DESC + i0 + tid] = ri1[tid];
    }
}

// ---- kernel 4/5: final cross-chunk reductions -----------------------------
__global__ void reduce_rows_kernel() {
    int i = blockIdx.x * blockDim.x + threadIdx.x;
    if (i >= N_DESC) return;
    float v1 = -2.f, v2 = -2.f; int i1 = 0;
    #pragma unroll
    for (int cc = 0; cc < CS; ++cc) {
        float w1 = g_rowV1[cc * N_DESC + i];
        float w2 = g_rowV2[cc * N_DESC + i];
        int   j1 = g_rowI1[cc * N_DESC + i];
        if (w1 > v1) { v2 = fmaxf(v1, w2); v1 = w1; i1 = j1; }
        else         { v2 = fmaxf(v2, w1); }
    }
    g_aV1[i] = v1; g_aV2[i] = v2; g_aI1[i] = i1;
}

__global__ void reduce_cols_kernel() {
    int j = blockIdx.x * blockDim.x + threadIdx.x;
    if (j >= N_DESC) return;
    float v1 = -2.f, v2 = -2.f; int i1 = 0;
    for (int rt = 0; rt < NROWTILES; ++rt) {
        float w1 = g_colV1[rt * N_DESC + j];
        float w2 = g_colV2[rt * N_DESC + j];
        int   j1 = g_colI1[rt * N_DESC + j];
        if (w1 > v1) { v2 = fmaxf(v1, w2); v1 = w1; i1 = j1; }
        else         { v2 = fmaxf(v2, w1); }
    }
    g_bV1[j] = v1; g_bV2[j] = v2; g_bI1[j] = i1;
}

// ---- kernel 6: mutual check + ratio test + output -------------------------
__global__ void match_kernel(float* __restrict__ out) {
    int i = blockIdx.x * blockDim.x + threadIdx.x;
    if (i >= N_DESC) return;
    float s1 = g_aV1[i], s2 = g_aV2[i];
    int   n12 = g_aI1[i];
    float r12 = (2.0f - 2.0f * s1) / (2.0f - 2.0f * s2 + EPS_T);
    int   n21 = g_bI1[n12];
    float r21 = (2.0f - 2.0f * g_bV1[n12]) / (2.0f - 2.0f * g_bV2[n12] + EPS_T);
    bool mask = (n21 == i) && (r12 <= RATIO_T) && (r21 <= RATIO_T);
    out[i]              = mask ? s1 : 0.0f;
    out[N_DESC + i]     = (float)n12;
    out[2 * N_DESC + i] = mask ? 1.0f : 0.0f;
}

// ---------------------------------------------------------------------------
extern "C" void kernel_launch(void* const* d_in, const int* in_sizes, int n_in,
                              void* d_out, int out_size) {
    const float* mA = (const float*)d_in[0];
    const float* mB = (const float*)d_in[1];
    float* out = (float*)d_out;

    dim3 nb(N_DESC / 256, 2);
    norms_kernel<<<nb, 256>>>(mA, mB);

    dim3 sb(N_DESC / 256, CH, 2);
    scale_kernel<<<sb, 256>>>(mA, mB);

    dim3 gb(NROWTILES, CS);
    gemm_top2_kernel<<<gb, NTHREADS>>>();

    reduce_rows_kernel<<<N_DESC / 256, 256>>>();
    reduce_cols_kernel<<<N_DESC / 256, 256>>>();
    match_kernel<<<N_DESC / 256, 256>>>(out);
}